// round 3
// baseline (speedup 1.0000x reference)
#include <cuda_runtime.h>

#define D_MODEL 1024
#define NHEADS  16
#define DK      64
#define BATCH   4
#define SEQ     2048
#define MROWS   (BATCH * SEQ)   // 8192

// -------- scratch (no allocations allowed; __device__ globals) --------
__device__ float g_q [MROWS * D_MODEL];
__device__ float g_k [MROWS * D_MODEL];
__device__ float g_v [MROWS * D_MODEL];
__device__ float g_ao[MROWS * D_MODEL];

// ======================================================================
// GEMM: C[M,N] = A[M,K] @ B[N,K]^T (+ bias[N])
// A row-major [M,K], B row-major [N,K] (nn.Linear weight layout).
// Tile 128x128x16, 256 threads, 8x8 per-thread micro-tile.
// ======================================================================
#define BM 128
#define BN 128
#define BKK 16

__global__ __launch_bounds__(256)
void gemm_abt(const float* __restrict__ A,
              const float* __restrict__ Bm,
              const float* __restrict__ bias,
              float* __restrict__ C,
              int M, int N, int K)
{
    __shared__ float As[BKK][BM];
    __shared__ float Bs[BKK][BN];

    const int tid = threadIdx.x;
    const int bm  = blockIdx.y * BM;
    const int bn  = blockIdx.x * BN;
    const int ty  = tid >> 4;    // 0..15
    const int tx  = tid & 15;    // 0..15

    float acc[8][8];
    #pragma unroll
    for (int i = 0; i < 8; i++)
        #pragma unroll
        for (int j = 0; j < 8; j++) acc[i][j] = 0.f;

    for (int k0 = 0; k0 < K; k0 += BKK) {
        // cooperative load: 128x16 tiles of A and B, 2 float4 per thread each
        #pragma unroll
        for (int i = 0; i < 2; i++) {
            int id  = tid * 2 + i;        // 0..511
            int row = id >> 2;            // 0..127
            int kc  = (id & 3) << 2;      // 0,4,8,12
            float4 va = *(const float4*)(A + (size_t)(bm + row) * K + k0 + kc);
            As[kc + 0][row] = va.x;
            As[kc + 1][row] = va.y;
            As[kc + 2][row] = va.z;
            As[kc + 3][row] = va.w;
            float4 vb = *(const float4*)(Bm + (size_t)(bn + row) * K + k0 + kc);
            Bs[kc + 0][row] = vb.x;
            Bs[kc + 1][row] = vb.y;
            Bs[kc + 2][row] = vb.z;
            Bs[kc + 3][row] = vb.w;
        }
        __syncthreads();

        #pragma unroll
        for (int k = 0; k < BKK; k++) {
            float a[8], b[8];
            #pragma unroll
            for (int i = 0; i < 8; i++) a[i] = As[k][ty * 8 + i];
            #pragma unroll
            for (int j = 0; j < 8; j++) b[j] = Bs[k][tx * 8 + j];
            #pragma unroll
            for (int i = 0; i < 8; i++)
                #pragma unroll
                for (int j = 0; j < 8; j++)
                    acc[i][j] = fmaf(a[i], b[j], acc[i][j]);
        }
        __syncthreads();
    }

    #pragma unroll
    for (int i = 0; i < 8; i++) {
        int r = bm + ty * 8 + i;
        #pragma unroll
        for (int j = 0; j < 8; j += 4) {
            int c = bn + tx * 8 + j;
            float4 v;
            v.x = acc[i][j + 0];
            v.y = acc[i][j + 1];
            v.z = acc[i][j + 2];
            v.w = acc[i][j + 3];
            if (bias) {
                v.x += bias[c + 0];
                v.y += bias[c + 1];
                v.z += bias[c + 2];
                v.w += bias[c + 3];
            }
            *(float4*)(C + (size_t)r * N + c) = v;
        }
    }
}

// ======================================================================
// Causal flash attention, fp32. One query per thread.
// Q/K/V in [B*S, H*DK] layout (head h occupies cols h*64..h*64+63).
// Block: 128 threads = 128 queries; iterate 32-key tiles with online softmax.
// ======================================================================
#define AQ 128
#define AK 32

__global__ __launch_bounds__(128)
void attn_kernel(const float* __restrict__ Q,
                 const float* __restrict__ Kg,
                 const float* __restrict__ Vg,
                 float* __restrict__ O,
                 int S)
{
    __shared__ float Ks[AK][DK];
    __shared__ float Vs[AK][DK];

    const int tid = threadIdx.x;
    const int bh  = blockIdx.y;       // b*16 + h
    const int b   = bh >> 4;
    const int h   = bh & 15;
    const int qi  = blockIdx.x * AQ + tid;

    const size_t base = (size_t)b * S * D_MODEL + (size_t)h * DK;
    const float* qp = Q + base + (size_t)qi * D_MODEL;

    float q[DK];
    #pragma unroll
    for (int i = 0; i < DK / 4; i++) {
        float4 v = *(const float4*)(qp + i * 4);
        q[i * 4 + 0] = v.x; q[i * 4 + 1] = v.y;
        q[i * 4 + 2] = v.z; q[i * 4 + 3] = v.w;
    }

    float o[DK];
    #pragma unroll
    for (int d = 0; d < DK; d++) o[d] = 0.f;
    float m = -1e30f, l = 0.f;

    const int qmax   = blockIdx.x * AQ + AQ - 1;
    const int ntiles = qmax / AK + 1;

    for (int t = 0; t < ntiles; t++) {
        const int k0 = t * AK;

        // load K and V tiles: 32 rows x 64 floats = 512 float4 each
        for (int i = tid; i < AK * DK / 4; i += 128) {
            int r = i >> 4;           // 0..31
            int c = (i & 15) << 2;    // 0..60
            *(float4*)(&Ks[r][c]) =
                *(const float4*)(Kg + base + (size_t)(k0 + r) * D_MODEL + c);
            *(float4*)(&Vs[r][c]) =
                *(const float4*)(Vg + base + (size_t)(k0 + r) * D_MODEL + c);
        }
        __syncthreads();

        float s[AK];
        #pragma unroll
        for (int j = 0; j < AK; j++) {
            float accs = 0.f;
            #pragma unroll
            for (int d = 0; d < DK; d++)
                accs = fmaf(q[d], Ks[j][d], accs);
            s[j] = accs * 0.125f;   // 1/sqrt(64)
        }

        // causal mask (only needed on/after diagonal tile)
        if (k0 + AK - 1 > qi) {
            #pragma unroll
            for (int j = 0; j < AK; j++)
                if (k0 + j > qi) s[j] = -1e30f;
        }

        float mt = m;
        #pragma unroll
        for (int j = 0; j < AK; j++) mt = fmaxf(mt, s[j]);
        float corr = __expf(m - mt);
        m = mt;
        l *= corr;
        #pragma unroll
        for (int d = 0; d < DK; d++) o[d] *= corr;

        #pragma unroll
        for (int j = 0; j < AK; j++) {
            float p = __expf(s[j] - m);
            l += p;
            #pragma unroll
            for (int d = 0; d < DK; d++)
                o[d] = fmaf(p, Vs[j][d], o[d]);
        }
        __syncthreads();
    }

    const float inv = 1.f / l;
    float* op = O + base + (size_t)qi * D_MODEL;
    #pragma unroll
    for (int i = 0; i < DK / 4; i++) {
        float4 v;
        v.x = o[i * 4 + 0] * inv;
        v.y = o[i * 4 + 1] * inv;
        v.z = o[i * 4 + 2] * inv;
        v.w = o[i * 4 + 3] * inv;
        *(float4*)(op + i * 4) = v;
    }
}

// ======================================================================
extern "C" void kernel_launch(void* const* d_in, const int* in_sizes, int n_in,
                              void* d_out, int out_size)
{
    const float* x   = (const float*)d_in[0];
    const float* w_q = (const float*)d_in[1];
    const float* w_k = (const float*)d_in[2];
    const float* w_v = (const float*)d_in[3];
    const float* w_o = (const float*)d_in[4];
    const float* b_o = (const float*)d_in[5];
    float* out = (float*)d_out;

    float *q, *k, *v, *ao;
    cudaGetSymbolAddress((void**)&q,  g_q);
    cudaGetSymbolAddress((void**)&k,  g_k);
    cudaGetSymbolAddress((void**)&v,  g_v);
    cudaGetSymbolAddress((void**)&ao, g_ao);

    dim3 ggrid(D_MODEL / BN, MROWS / BM);   // (8, 64)

    gemm_abt<<<ggrid, 256>>>(x, w_q, nullptr, q, MROWS, D_MODEL, D_MODEL);
    gemm_abt<<<ggrid, 256>>>(x, w_k, nullptr, k, MROWS, D_MODEL, D_MODEL);
    gemm_abt<<<ggrid, 256>>>(x, w_v, nullptr, v, MROWS, D_MODEL, D_MODEL);

    dim3 agrid(SEQ / AQ, BATCH * NHEADS);   // (16, 64)
    attn_kernel<<<agrid, 128>>>(q, k, v, ao, SEQ);

    gemm_abt<<<ggrid, 256>>>(ao, w_o, b_o, out, MROWS, D_MODEL, D_MODEL);
}

// round 6
// speedup vs baseline: 1.4193x; 1.4193x over previous
#include <cuda_runtime.h>
#include <cuda_bf16.h>
#include <cstdint>

#define D_MODEL 1024
#define NHEADS  16
#define DK      64
#define BATCH   4
#define SEQ     2048
#define MROWS   (BATCH * SEQ)   // 8192

// -------- scratch (no allocations allowed; __device__ globals) --------
__device__ float g_q [MROWS * D_MODEL];
__device__ float g_k [MROWS * D_MODEL];
__device__ float g_v [MROWS * D_MODEL];
__device__ float g_ao[MROWS * D_MODEL];

// ======================================================================
// helpers
// ======================================================================
__device__ __forceinline__ uint32_t smem_u32(const void* p) {
    uint32_t a;
    asm("{ .reg .u64 t; cvta.to.shared.u64 t, %1; cvt.u32.u64 %0, t; }"
        : "=r"(a) : "l"(p));
    return a;
}

#define LDSM_X4(r0, r1, r2, r3, addr)                                         \
    asm volatile("ldmatrix.sync.aligned.m8n8.x4.shared.b16 {%0,%1,%2,%3}, [%4];" \
                 : "=r"(r0), "=r"(r1), "=r"(r2), "=r"(r3) : "r"(addr))

#define MMA16816(d, a, b0v, b1v)                                              \
    asm volatile("mma.sync.aligned.m16n8k16.row.col.f32.bf16.bf16.f32 "       \
                 "{%0,%1,%2,%3}, {%4,%5,%6,%7}, {%8,%9}, {%0,%1,%2,%3};"      \
                 : "+f"((d)[0]), "+f"((d)[1]), "+f"((d)[2]), "+f"((d)[3])     \
                 : "r"((a)[0]), "r"((a)[1]), "r"((a)[2]), "r"((a)[3]),        \
                   "r"(b0v), "r"(b1v))

// split one float pair into bf16 hi + bf16 lo packed u32s
__device__ __forceinline__ void split2(float x, float y, uint32_t& hi, uint32_t& lo) {
    __nv_bfloat162 h = __floats2bfloat162_rn(x, y);
    float2 f = __bfloat1622float2(h);
    __nv_bfloat162 l = __floats2bfloat162_rn(x - f.x, y - f.y);
    hi = *reinterpret_cast<uint32_t*>(&h);
    lo = *reinterpret_cast<uint32_t*>(&l);
}

// ======================================================================
// HMMA GEMM: C[M,N] = A[M,K] @ B[N,K]^T (+bias), fp32 via bf16x3 split.
// CTA tile 128x128, BK=32, 8 warps (warp tile 32x64), m16n8k16 atoms.
// SMEM rows padded to 80B pitch -> conflict-free ldmatrix. Double buffered.
// ======================================================================
#define GPITCH 80                      // bytes per 32-bf16 row (64B + 16B pad)
#define GBK    32
#define GNIT   (D_MODEL / GBK)         // 32
#define MAT_B  (128 * GPITCH)          // 10240 B per matrix tile
#define BUF_B  (4 * MAT_B)             // Ah, Al, Bh, Bl
#define GSMEM  (2 * BUF_B)             // 81920

__global__ __launch_bounds__(256)
void gemm_mma(const float* __restrict__ A,
              const float* __restrict__ Bm,
              const float* __restrict__ bias,
              float* __restrict__ C)
{
    extern __shared__ char sm[];
    const uint32_t sbase = smem_u32(sm);

    const int tid    = threadIdx.x;
    const int lane   = tid & 31;
    const int wid    = tid >> 5;
    const int warp_m = wid & 3;        // 0..3  -> 32 M-rows each
    const int warp_n = wid >> 2;       // 0..1  -> 64 N-cols each
    const int bm     = blockIdx.y * 128;
    const int bn     = blockIdx.x * 128;

    // gmem load assignment: thread -> (row = tid>>1, 16 floats at col (tid&1)*16)
    const int lrow = tid >> 1;
    const int lcol = (tid & 1) * 16;
    const float* ap = A  + (size_t)(bm + lrow) * D_MODEL + lcol;
    const float* bp = Bm + (size_t)(bn + lrow) * D_MODEL + lcol;
    const uint32_t srow = (uint32_t)lrow * GPITCH + (uint32_t)(lcol * 2);

    float acc[2][8][4];
    #pragma unroll
    for (int i = 0; i < 2; i++)
        #pragma unroll
        for (int j = 0; j < 8; j++)
            #pragma unroll
            for (int r = 0; r < 4; r++) acc[i][j][r] = 0.f;

    // fragment-load base addresses (buffer offset added per iter)
    const uint32_t a_l = sbase + (uint32_t)((warp_m * 32 + (lane & 15)) * GPITCH
                                            + (lane >> 4) * 16);
    const int bnl = warp_n * 64 + (lane & 7) + ((lane >> 4) << 3);
    const uint32_t b_l = sbase + 2 * MAT_B + (uint32_t)(bnl * GPITCH
                                            + ((lane >> 3) & 1) * 16);

    float4 av[4], bv[4];

    // prologue: load tile 0
    #pragma unroll
    for (int j = 0; j < 4; j++) {
        av[j] = *(const float4*)(ap + j * 4);
        bv[j] = *(const float4*)(bp + j * 4);
    }

    #pragma unroll 1
    for (int it = 0; it < GNIT; it++) {
        const uint32_t bufo = (uint32_t)(it & 1) * BUF_B;

        // stage regs -> smem (split hi/lo)
        {
            char* d = sm + bufo;
            uint32_t h[8], l[8];
            #pragma unroll
            for (int j = 0; j < 4; j++) {
                split2(av[j].x, av[j].y, h[2 * j + 0], l[2 * j + 0]);
                split2(av[j].z, av[j].w, h[2 * j + 1], l[2 * j + 1]);
            }
            *(uint4*)(d + srow)              = make_uint4(h[0], h[1], h[2], h[3]);
            *(uint4*)(d + srow + 16)         = make_uint4(h[4], h[5], h[6], h[7]);
            *(uint4*)(d + MAT_B + srow)      = make_uint4(l[0], l[1], l[2], l[3]);
            *(uint4*)(d + MAT_B + srow + 16) = make_uint4(l[4], l[5], l[6], l[7]);
            #pragma unroll
            for (int j = 0; j < 4; j++) {
                split2(bv[j].x, bv[j].y, h[2 * j + 0], l[2 * j + 0]);
                split2(bv[j].z, bv[j].w, h[2 * j + 1], l[2 * j + 1]);
            }
            *(uint4*)(d + 2 * MAT_B + srow)      = make_uint4(h[0], h[1], h[2], h[3]);
            *(uint4*)(d + 2 * MAT_B + srow + 16) = make_uint4(h[4], h[5], h[6], h[7]);
            *(uint4*)(d + 3 * MAT_B + srow)      = make_uint4(l[0], l[1], l[2], l[3]);
            *(uint4*)(d + 3 * MAT_B + srow + 16) = make_uint4(l[4], l[5], l[6], l[7]);
        }
        __syncthreads();

        // prefetch next tile while doing MMA on this one
        if (it + 1 < GNIT) {
            const float* apn = ap + (it + 1) * GBK;
            const float* bpn = bp + (it + 1) * GBK;
            #pragma unroll
            for (int j = 0; j < 4; j++) {
                av[j] = *(const float4*)(apn + j * 4);
                bv[j] = *(const float4*)(bpn + j * 4);
            }
        }

        #pragma unroll
        for (int ks = 0; ks < 2; ks++) {
            const uint32_t ko = (uint32_t)(ks * 32);
            uint32_t ah[2][4], al[2][4];
            #pragma unroll
            for (int im = 0; im < 2; im++) {
                uint32_t aa = a_l + bufo + ko + (uint32_t)(im * 16 * GPITCH);
                LDSM_X4(ah[im][0], ah[im][1], ah[im][2], ah[im][3], aa);
                LDSM_X4(al[im][0], al[im][1], al[im][2], al[im][3], aa + MAT_B);
            }
            uint32_t bh[16], bl[16];
            #pragma unroll
            for (int pn = 0; pn < 4; pn++) {
                uint32_t ba = b_l + bufo + ko + (uint32_t)(pn * 16 * GPITCH);
                LDSM_X4(bh[4 * pn + 0], bh[4 * pn + 1], bh[4 * pn + 2], bh[4 * pn + 3], ba);
                LDSM_X4(bl[4 * pn + 0], bl[4 * pn + 1], bl[4 * pn + 2], bl[4 * pn + 3], ba + MAT_B);
            }
            #pragma unroll
            for (int im = 0; im < 2; im++)
                #pragma unroll
                for (int in = 0; in < 8; in++) {
                    MMA16816(acc[im][in], ah[im], bh[2 * in], bh[2 * in + 1]);
                    MMA16816(acc[im][in], ah[im], bl[2 * in], bl[2 * in + 1]);
                    MMA16816(acc[im][in], al[im], bh[2 * in], bh[2 * in + 1]);
                }
        }
        __syncthreads();
    }

    // epilogue: fragment -> gmem (+bias)
    const int g = lane >> 2;
    const int q4 = (lane & 3) * 2;
    #pragma unroll
    for (int im = 0; im < 2; im++) {
        const int r0 = bm + warp_m * 32 + im * 16 + g;
        #pragma unroll
        for (int in = 0; in < 8; in++) {
            const int c = bn + warp_n * 64 + in * 8 + q4;
            float b0 = 0.f, b1 = 0.f;
            if (bias) { b0 = bias[c]; b1 = bias[c + 1]; }
            float2 v0 = make_float2(acc[im][in][0] + b0, acc[im][in][1] + b1);
            float2 v1 = make_float2(acc[im][in][2] + b0, acc[im][in][3] + b1);
            *(float2*)(C + (size_t)r0 * D_MODEL + c)       = v0;
            *(float2*)(C + (size_t)(r0 + 8) * D_MODEL + c) = v1;
        }
    }
}

// ======================================================================
// Causal flash attention, fp32 (unchanged — R5 target).
// ======================================================================
#define AQ 128
#define AK 32

__global__ __launch_bounds__(128)
void attn_kernel(const float* __restrict__ Q,
                 const float* __restrict__ Kg,
                 const float* __restrict__ Vg,
                 float* __restrict__ O,
                 int S)
{
    __shared__ float Ks[AK][DK];
    __shared__ float Vs[AK][DK];

    const int tid = threadIdx.x;
    const int bh  = blockIdx.y;
    const int b   = bh >> 4;
    const int h   = bh & 15;
    const int qi  = blockIdx.x * AQ + tid;

    const size_t base = (size_t)b * S * D_MODEL + (size_t)h * DK;
    const float* qp = Q + base + (size_t)qi * D_MODEL;

    float q[DK];
    #pragma unroll
    for (int i = 0; i < DK / 4; i++) {
        float4 v = *(const float4*)(qp + i * 4);
        q[i * 4 + 0] = v.x; q[i * 4 + 1] = v.y;
        q[i * 4 + 2] = v.z; q[i * 4 + 3] = v.w;
    }

    float o[DK];
    #pragma unroll
    for (int d = 0; d < DK; d++) o[d] = 0.f;
    float m = -1e30f, l = 0.f;

    const int qmax   = blockIdx.x * AQ + AQ - 1;
    const int ntiles = qmax / AK + 1;

    for (int t = 0; t < ntiles; t++) {
        const int k0 = t * AK;

        for (int i = tid; i < AK * DK / 4; i += 128) {
            int r = i >> 4;
            int c = (i & 15) << 2;
            *(float4*)(&Ks[r][c]) =
                *(const float4*)(Kg + base + (size_t)(k0 + r) * D_MODEL + c);
            *(float4*)(&Vs[r][c]) =
                *(const float4*)(Vg + base + (size_t)(k0 + r) * D_MODEL + c);
        }
        __syncthreads();

        float s[AK];
        #pragma unroll
        for (int j = 0; j < AK; j++) {
            float accs = 0.f;
            #pragma unroll
            for (int d = 0; d < DK; d++)
                accs = fmaf(q[d], Ks[j][d], accs);
            s[j] = accs * 0.125f;
        }

        if (k0 + AK - 1 > qi) {
            #pragma unroll
            for (int j = 0; j < AK; j++)
                if (k0 + j > qi) s[j] = -1e30f;
        }

        float mt = m;
        #pragma unroll
        for (int j = 0; j < AK; j++) mt = fmaxf(mt, s[j]);
        float corr = __expf(m - mt);
        m = mt;
        l *= corr;
        #pragma unroll
        for (int d = 0; d < DK; d++) o[d] *= corr;

        #pragma unroll
        for (int j = 0; j < AK; j++) {
            float p = __expf(s[j] - m);
            l += p;
            #pragma unroll
            for (int d = 0; d < DK; d++)
                o[d] = fmaf(p, Vs[j][d], o[d]);
        }
        __syncthreads();
    }

    const float inv = 1.f / l;
    float* op = O + base + (size_t)qi * D_MODEL;
    #pragma unroll
    for (int i = 0; i < DK / 4; i++) {
        float4 v;
        v.x = o[i * 4 + 0] * inv;
        v.y = o[i * 4 + 1] * inv;
        v.z = o[i * 4 + 2] * inv;
        v.w = o[i * 4 + 3] * inv;
        *(float4*)(op + i * 4) = v;
    }
}

// ======================================================================
extern "C" void kernel_launch(void* const* d_in, const int* in_sizes, int n_in,
                              void* d_out, int out_size)
{
    const float* x   = (const float*)d_in[0];
    const float* w_q = (const float*)d_in[1];
    const float* w_k = (const float*)d_in[2];
    const float* w_v = (const float*)d_in[3];
    const float* w_o = (const float*)d_in[4];
    const float* b_o = (const float*)d_in[5];
    float* out = (float*)d_out;

    float *q, *k, *v, *ao;
    cudaGetSymbolAddress((void**)&q,  g_q);
    cudaGetSymbolAddress((void**)&k,  g_k);
    cudaGetSymbolAddress((void**)&v,  g_v);
    cudaGetSymbolAddress((void**)&ao, g_ao);

    cudaFuncSetAttribute(gemm_mma, cudaFuncAttributeMaxDynamicSharedMemorySize, GSMEM);

    dim3 ggrid(D_MODEL / 128, MROWS / 128);   // (8, 64)

    gemm_mma<<<ggrid, 256, GSMEM>>>(x, w_q, nullptr, q);
    gemm_mma<<<ggrid, 256, GSMEM>>>(x, w_k, nullptr, k);
    gemm_mma<<<ggrid, 256, GSMEM>>>(x, w_v, nullptr, v);

    dim3 agrid(SEQ / AQ, BATCH * NHEADS);     // (16, 64)
    attn_kernel<<<agrid, 128>>>(q, k, v, ao, SEQ);

    gemm_mma<<<ggrid, 256, GSMEM>>>(ao, w_o, b_o, out);
}

// round 7
// speedup vs baseline: 2.0158x; 1.4203x over previous
#include <cuda_runtime.h>
#include <cuda_bf16.h>
#include <cstdint>

#define D_MODEL 1024
#define NHEADS  16
#define DK      64
#define BATCH   4
#define SEQ     2048
#define MROWS   (BATCH * SEQ)   // 8192

// -------- scratch (no allocations allowed; __device__ globals) --------
__device__ float g_q [MROWS * D_MODEL];
__device__ float g_k [MROWS * D_MODEL];
__device__ float g_v [MROWS * D_MODEL];
__device__ float g_ao[MROWS * D_MODEL];

// ======================================================================
// helpers
// ======================================================================
__device__ __forceinline__ uint32_t smem_u32(const void* p) {
    uint32_t a;
    asm("{ .reg .u64 t; cvta.to.shared.u64 t, %1; cvt.u32.u64 %0, t; }"
        : "=r"(a) : "l"(p));
    return a;
}

#define LDSM_X4(r0, r1, r2, r3, addr)                                         \
    asm volatile("ldmatrix.sync.aligned.m8n8.x4.shared.b16 {%0,%1,%2,%3}, [%4];" \
                 : "=r"(r0), "=r"(r1), "=r"(r2), "=r"(r3) : "r"(addr))

#define LDSM_X4_T(r0, r1, r2, r3, addr)                                       \
    asm volatile("ldmatrix.sync.aligned.m8n8.x4.trans.shared.b16 {%0,%1,%2,%3}, [%4];" \
                 : "=r"(r0), "=r"(r1), "=r"(r2), "=r"(r3) : "r"(addr))

#define MMA16816(d, a, b0v, b1v)                                              \
    asm volatile("mma.sync.aligned.m16n8k16.row.col.f32.bf16.bf16.f32 "       \
                 "{%0,%1,%2,%3}, {%4,%5,%6,%7}, {%8,%9}, {%0,%1,%2,%3};"      \
                 : "+f"((d)[0]), "+f"((d)[1]), "+f"((d)[2]), "+f"((d)[3])     \
                 : "r"((a)[0]), "r"((a)[1]), "r"((a)[2]), "r"((a)[3]),        \
                   "r"(b0v), "r"(b1v))

// split one float pair into bf16 hi + bf16 lo packed u32s
__device__ __forceinline__ void split2(float x, float y, uint32_t& hi, uint32_t& lo) {
    __nv_bfloat162 h = __floats2bfloat162_rn(x, y);
    float2 f = __bfloat1622float2(h);
    __nv_bfloat162 l = __floats2bfloat162_rn(x - f.x, y - f.y);
    hi = *reinterpret_cast<uint32_t*>(&h);
    lo = *reinterpret_cast<uint32_t*>(&l);
}

// ======================================================================
// HMMA GEMM (unchanged from R5): C = A @ B^T (+bias), bf16x3 split.
// ======================================================================
#define GPITCH 80
#define GBK    32
#define GNIT   (D_MODEL / GBK)
#define MAT_B  (128 * GPITCH)
#define BUF_B  (4 * MAT_B)
#define GSMEM  (2 * BUF_B)

__global__ __launch_bounds__(256)
void gemm_mma(const float* __restrict__ A,
              const float* __restrict__ Bm,
              const float* __restrict__ bias,
              float* __restrict__ C)
{
    extern __shared__ char sm[];
    const uint32_t sbase = smem_u32(sm);

    const int tid    = threadIdx.x;
    const int lane   = tid & 31;
    const int wid    = tid >> 5;
    const int warp_m = wid & 3;
    const int warp_n = wid >> 2;
    const int bm     = blockIdx.y * 128;
    const int bn     = blockIdx.x * 128;

    const int lrow = tid >> 1;
    const int lcol = (tid & 1) * 16;
    const float* ap = A  + (size_t)(bm + lrow) * D_MODEL + lcol;
    const float* bp = Bm + (size_t)(bn + lrow) * D_MODEL + lcol;
    const uint32_t srow = (uint32_t)lrow * GPITCH + (uint32_t)(lcol * 2);

    float acc[2][8][4];
    #pragma unroll
    for (int i = 0; i < 2; i++)
        #pragma unroll
        for (int j = 0; j < 8; j++)
            #pragma unroll
            for (int r = 0; r < 4; r++) acc[i][j][r] = 0.f;

    const uint32_t a_l = sbase + (uint32_t)((warp_m * 32 + (lane & 15)) * GPITCH
                                            + (lane >> 4) * 16);
    const int bnl = warp_n * 64 + (lane & 7) + ((lane >> 4) << 3);
    const uint32_t b_l = sbase + 2 * MAT_B + (uint32_t)(bnl * GPITCH
                                            + ((lane >> 3) & 1) * 16);

    float4 av[4], bv[4];
    #pragma unroll
    for (int j = 0; j < 4; j++) {
        av[j] = *(const float4*)(ap + j * 4);
        bv[j] = *(const float4*)(bp + j * 4);
    }

    #pragma unroll 1
    for (int it = 0; it < GNIT; it++) {
        const uint32_t bufo = (uint32_t)(it & 1) * BUF_B;
        {
            char* d = sm + bufo;
            uint32_t h[8], l[8];
            #pragma unroll
            for (int j = 0; j < 4; j++) {
                split2(av[j].x, av[j].y, h[2 * j + 0], l[2 * j + 0]);
                split2(av[j].z, av[j].w, h[2 * j + 1], l[2 * j + 1]);
            }
            *(uint4*)(d + srow)              = make_uint4(h[0], h[1], h[2], h[3]);
            *(uint4*)(d + srow + 16)         = make_uint4(h[4], h[5], h[6], h[7]);
            *(uint4*)(d + MAT_B + srow)      = make_uint4(l[0], l[1], l[2], l[3]);
            *(uint4*)(d + MAT_B + srow + 16) = make_uint4(l[4], l[5], l[6], l[7]);
            #pragma unroll
            for (int j = 0; j < 4; j++) {
                split2(bv[j].x, bv[j].y, h[2 * j + 0], l[2 * j + 0]);
                split2(bv[j].z, bv[j].w, h[2 * j + 1], l[2 * j + 1]);
            }
            *(uint4*)(d + 2 * MAT_B + srow)      = make_uint4(h[0], h[1], h[2], h[3]);
            *(uint4*)(d + 2 * MAT_B + srow + 16) = make_uint4(h[4], h[5], h[6], h[7]);
            *(uint4*)(d + 3 * MAT_B + srow)      = make_uint4(l[0], l[1], l[2], l[3]);
            *(uint4*)(d + 3 * MAT_B + srow + 16) = make_uint4(l[4], l[5], l[6], l[7]);
        }
        __syncthreads();

        if (it + 1 < GNIT) {
            const float* apn = ap + (it + 1) * GBK;
            const float* bpn = bp + (it + 1) * GBK;
            #pragma unroll
            for (int j = 0; j < 4; j++) {
                av[j] = *(const float4*)(apn + j * 4);
                bv[j] = *(const float4*)(bpn + j * 4);
            }
        }

        #pragma unroll
        for (int ks = 0; ks < 2; ks++) {
            const uint32_t ko = (uint32_t)(ks * 32);
            uint32_t ah[2][4], al[2][4];
            #pragma unroll
            for (int im = 0; im < 2; im++) {
                uint32_t aa = a_l + bufo + ko + (uint32_t)(im * 16 * GPITCH);
                LDSM_X4(ah[im][0], ah[im][1], ah[im][2], ah[im][3], aa);
                LDSM_X4(al[im][0], al[im][1], al[im][2], al[im][3], aa + MAT_B);
            }
            uint32_t bh[16], bl[16];
            #pragma unroll
            for (int pn = 0; pn < 4; pn++) {
                uint32_t ba = b_l + bufo + ko + (uint32_t)(pn * 16 * GPITCH);
                LDSM_X4(bh[4 * pn + 0], bh[4 * pn + 1], bh[4 * pn + 2], bh[4 * pn + 3], ba);
                LDSM_X4(bl[4 * pn + 0], bl[4 * pn + 1], bl[4 * pn + 2], bl[4 * pn + 3], ba + MAT_B);
            }
            #pragma unroll
            for (int im = 0; im < 2; im++)
                #pragma unroll
                for (int in = 0; in < 8; in++) {
                    MMA16816(acc[im][in], ah[im], bh[2 * in], bh[2 * in + 1]);
                    MMA16816(acc[im][in], ah[im], bl[2 * in], bl[2 * in + 1]);
                    MMA16816(acc[im][in], al[im], bh[2 * in], bh[2 * in + 1]);
                }
        }
        __syncthreads();
    }

    const int g = lane >> 2;
    const int q4 = (lane & 3) * 2;
    #pragma unroll
    for (int im = 0; im < 2; im++) {
        const int r0 = bm + warp_m * 32 + im * 16 + g;
        #pragma unroll
        for (int in = 0; in < 8; in++) {
            const int c = bn + warp_n * 64 + in * 8 + q4;
            float b0 = 0.f, b1 = 0.f;
            if (bias) { b0 = bias[c]; b1 = bias[c + 1]; }
            float2 v0 = make_float2(acc[im][in][0] + b0, acc[im][in][1] + b1);
            float2 v1 = make_float2(acc[im][in][2] + b0, acc[im][in][3] + b1);
            *(float2*)(C + (size_t)r0 * D_MODEL + c)       = v0;
            *(float2*)(C + (size_t)(r0 + 8) * D_MODEL + c) = v1;
        }
    }
}

// ======================================================================
// Tensor-core causal flash attention, bf16x3 split for QK and PV.
// CTA: 128 queries x one (b,h). 8 warps, m16 warp tiles. Key tiles of 64.
// SMEM pitch 144B (64 bf16 + 16B pad) -> conflict-free ldmatrix.
// ======================================================================
#define APITCH 144
#define SQH 0
#define SQL (SQH + 128 * APITCH)        // 18432
#define SKH (SQL + 128 * APITCH)        // 36864
#define SKL (SKH + 64 * APITCH)         // 46080
#define SVH (SKL + 64 * APITCH)        // 55296
#define SVL (SVH + 64 * APITCH)        // 64512
#define ASMEM (SVL + 64 * APITCH)      // 73728

__global__ __launch_bounds__(256)
void attn_mma(const float* __restrict__ Q,
              const float* __restrict__ Kg,
              const float* __restrict__ Vg,
              float* __restrict__ O)
{
    extern __shared__ char sm[];
    const uint32_t sbase = smem_u32(sm);

    const int tid  = threadIdx.x;
    const int lane = tid & 31;
    const int wid  = tid >> 5;          // 0..7
    const int g    = lane >> 2;         // row-in-8
    const int tg   = lane & 3;          // col pair
    const int qb   = blockIdx.x;        // query block (128 rows)
    const int bh   = blockIdx.y;
    const size_t base = (size_t)(bh >> 4) * SEQ * D_MODEL + (size_t)(bh & 15) * DK;

    const int qbase = qb * 128 + wid * 16;   // this warp's first query row

    // ---- stage Q (once): pre-scaled by 1/8, split hi/lo ----
    {
        const int r  = tid >> 1;
        const int cf = (tid & 1) * 32;
        const float* qp = Q + base + (size_t)(qb * 128 + r) * D_MODEL + cf;
        uint32_t h[16], l[16];
        #pragma unroll
        for (int j = 0; j < 8; j++) {
            float4 v = *(const float4*)(qp + j * 4);
            v.x *= 0.125f; v.y *= 0.125f; v.z *= 0.125f; v.w *= 0.125f;
            split2(v.x, v.y, h[2 * j + 0], l[2 * j + 0]);
            split2(v.z, v.w, h[2 * j + 1], l[2 * j + 1]);
        }
        char* dq = sm + r * APITCH + cf * 2;
        #pragma unroll
        for (int j = 0; j < 4; j++) {
            *(uint4*)(dq + SQH + j * 16) = make_uint4(h[4*j], h[4*j+1], h[4*j+2], h[4*j+3]);
            *(uint4*)(dq + SQL + j * 16) = make_uint4(l[4*j], l[4*j+1], l[4*j+2], l[4*j+3]);
        }
    }

    float oacc[8][4];
    #pragma unroll
    for (int i = 0; i < 8; i++)
        #pragma unroll
        for (int r = 0; r < 4; r++) oacc[i][r] = 0.f;
    float m0 = -1e30f, m1 = -1e30f, l0 = 0.f, l1 = 0.f;

    // fragment addresses
    const uint32_t qa = sbase + (uint32_t)((wid * 16 + (lane & 15)) * APITCH
                                           + (lane >> 4) * 16);
    const uint32_t ka = sbase + SKH + (uint32_t)(((lane & 7) + ((lane >> 4) << 3)) * APITCH
                                           + ((lane >> 3) & 1) * 16);
    const uint32_t va = sbase + SVH + (uint32_t)((lane & 15) * APITCH + (lane >> 4) * 16);

    const int ntiles = 2 * qb + 2;

    #pragma unroll 1
    for (int t = 0; t < ntiles; t++) {
        const int k0 = t * 64;

        // ---- stage K/V tile (all 256 threads) ----
        {
            const int r  = tid >> 2;
            const int cf = (tid & 3) * 16;
            const float* kp = Kg + base + (size_t)(k0 + r) * D_MODEL + cf;
            const float* vp = Vg + base + (size_t)(k0 + r) * D_MODEL + cf;
            uint32_t h[8], l[8];
            char* dk = sm + r * APITCH + cf * 2;
            #pragma unroll
            for (int j = 0; j < 4; j++) {
                float4 v = *(const float4*)(kp + j * 4);
                split2(v.x, v.y, h[2*j+0], l[2*j+0]);
                split2(v.z, v.w, h[2*j+1], l[2*j+1]);
            }
            *(uint4*)(dk + SKH)      = make_uint4(h[0], h[1], h[2], h[3]);
            *(uint4*)(dk + SKH + 16) = make_uint4(h[4], h[5], h[6], h[7]);
            *(uint4*)(dk + SKL)      = make_uint4(l[0], l[1], l[2], l[3]);
            *(uint4*)(dk + SKL + 16) = make_uint4(l[4], l[5], l[6], l[7]);
            #pragma unroll
            for (int j = 0; j < 4; j++) {
                float4 v = *(const float4*)(vp + j * 4);
                split2(v.x, v.y, h[2*j+0], l[2*j+0]);
                split2(v.z, v.w, h[2*j+1], l[2*j+1]);
            }
            *(uint4*)(dk + SVH)      = make_uint4(h[0], h[1], h[2], h[3]);
            *(uint4*)(dk + SVH + 16) = make_uint4(h[4], h[5], h[6], h[7]);
            *(uint4*)(dk + SVL)      = make_uint4(l[0], l[1], l[2], l[3]);
            *(uint4*)(dk + SVL + 16) = make_uint4(l[4], l[5], l[6], l[7]);
        }
        __syncthreads();

        const bool active = (k0 <= qbase + 15);
        if (active) {
            // ---- S = Q @ K^T (3-term split), keys n = 64 ----
            float sacc[8][4];
            #pragma unroll
            for (int i = 0; i < 8; i++)
                #pragma unroll
                for (int r = 0; r < 4; r++) sacc[i][r] = 0.f;

            #pragma unroll
            for (int kk = 0; kk < 4; kk++) {
                const uint32_t ko = (uint32_t)(kk * 32);
                uint32_t ah[4], al[4];
                LDSM_X4(ah[0], ah[1], ah[2], ah[3], qa + ko);
                LDSM_X4(al[0], al[1], al[2], al[3], qa + ko + (SQL - SQH));
                #pragma unroll
                for (int nt = 0; nt < 4; nt++) {
                    uint32_t ba = ka + ko + (uint32_t)(nt * 16 * APITCH);
                    uint32_t kh[4], kl[4];
                    LDSM_X4(kh[0], kh[1], kh[2], kh[3], ba);
                    LDSM_X4(kl[0], kl[1], kl[2], kl[3], ba + (SKL - SKH));
                    MMA16816(sacc[2*nt],   ah, kh[0], kh[1]);
                    MMA16816(sacc[2*nt],   ah, kl[0], kl[1]);
                    MMA16816(sacc[2*nt],   al, kh[0], kh[1]);
                    MMA16816(sacc[2*nt+1], ah, kh[2], kh[3]);
                    MMA16816(sacc[2*nt+1], ah, kl[2], kl[3]);
                    MMA16816(sacc[2*nt+1], al, kh[2], kh[3]);
                }
            }

            // ---- causal mask (only last two tiles can intersect diagonal) ----
            if (t + 2 >= ntiles) {
                const int qi0 = qbase + g;
                const int qi1 = qbase + g + 8;
                #pragma unroll
                for (int dn = 0; dn < 8; dn++) {
                    const int kc = k0 + dn * 8 + tg * 2;
                    if (kc     > qi0) sacc[dn][0] = -1e30f;
                    if (kc + 1 > qi0) sacc[dn][1] = -1e30f;
                    if (kc     > qi1) sacc[dn][2] = -1e30f;
                    if (kc + 1 > qi1) sacc[dn][3] = -1e30f;
                }
            }

            // ---- online softmax (row stats per lane, quad-reduced max) ----
            float r0 = -1e30f, r1 = -1e30f;
            #pragma unroll
            for (int dn = 0; dn < 8; dn++) {
                r0 = fmaxf(r0, fmaxf(sacc[dn][0], sacc[dn][1]));
                r1 = fmaxf(r1, fmaxf(sacc[dn][2], sacc[dn][3]));
            }
            r0 = fmaxf(r0, __shfl_xor_sync(0xFFFFFFFFu, r0, 1));
            r0 = fmaxf(r0, __shfl_xor_sync(0xFFFFFFFFu, r0, 2));
            r1 = fmaxf(r1, __shfl_xor_sync(0xFFFFFFFFu, r1, 1));
            r1 = fmaxf(r1, __shfl_xor_sync(0xFFFFFFFFu, r1, 2));
            const float nm0 = fmaxf(m0, r0), nm1 = fmaxf(m1, r1);
            const float c0 = __expf(m0 - nm0), c1 = __expf(m1 - nm1);
            m0 = nm0; m1 = nm1;
            l0 *= c0;  l1 *= c1;
            #pragma unroll
            for (int dn = 0; dn < 8; dn++) {
                oacc[dn][0] *= c0; oacc[dn][1] *= c0;
                oacc[dn][2] *= c1; oacc[dn][3] *= c1;
            }
            #pragma unroll
            for (int dn = 0; dn < 8; dn++) {
                float p0 = __expf(sacc[dn][0] - m0);
                float p1 = __expf(sacc[dn][1] - m0);
                float p2 = __expf(sacc[dn][2] - m1);
                float p3 = __expf(sacc[dn][3] - m1);
                sacc[dn][0] = p0; sacc[dn][1] = p1;
                sacc[dn][2] = p2; sacc[dn][3] = p3;
                l0 += p0 + p1; l1 += p2 + p3;
            }

            // ---- O += P @ V (3-term split), k = keys ----
            #pragma unroll
            for (int kk = 0; kk < 4; kk++) {
                uint32_t ph[4], pl[4];
                split2(sacc[2*kk][0],   sacc[2*kk][1],   ph[0], pl[0]);
                split2(sacc[2*kk][2],   sacc[2*kk][3],   ph[1], pl[1]);
                split2(sacc[2*kk+1][0], sacc[2*kk+1][1], ph[2], pl[2]);
                split2(sacc[2*kk+1][2], sacc[2*kk+1][3], ph[3], pl[3]);
                #pragma unroll
                for (int dn = 0; dn < 4; dn++) {
                    uint32_t a = va + (uint32_t)(kk * 16 * APITCH + dn * 32);
                    uint32_t vh[4], vl[4];
                    LDSM_X4_T(vh[0], vh[1], vh[2], vh[3], a);
                    LDSM_X4_T(vl[0], vl[1], vl[2], vl[3], a + (SVL - SVH));
                    MMA16816(oacc[2*dn],   ph, vh[0], vh[1]);
                    MMA16816(oacc[2*dn],   ph, vl[0], vl[1]);
                    MMA16816(oacc[2*dn],   pl, vh[0], vh[1]);
                    MMA16816(oacc[2*dn+1], ph, vh[2], vh[3]);
                    MMA16816(oacc[2*dn+1], ph, vl[2], vl[3]);
                    MMA16816(oacc[2*dn+1], pl, vh[2], vh[3]);
                }
            }
        }
        __syncthreads();
    }

    // ---- epilogue: normalize and store ----
    l0 += __shfl_xor_sync(0xFFFFFFFFu, l0, 1);
    l0 += __shfl_xor_sync(0xFFFFFFFFu, l0, 2);
    l1 += __shfl_xor_sync(0xFFFFFFFFu, l1, 1);
    l1 += __shfl_xor_sync(0xFFFFFFFFu, l1, 2);
    const float inv0 = 1.f / l0, inv1 = 1.f / l1;

    float* orow0 = O + base + (size_t)(qbase + g) * D_MODEL + tg * 2;
    float* orow1 = orow0 + 8 * D_MODEL;
    #pragma unroll
    for (int dn = 0; dn < 8; dn++) {
        *(float2*)(orow0 + dn * 8) = make_float2(oacc[dn][0] * inv0, oacc[dn][1] * inv0);
        *(float2*)(orow1 + dn * 8) = make_float2(oacc[dn][2] * inv1, oacc[dn][3] * inv1);
    }
}

// ======================================================================
extern "C" void kernel_launch(void* const* d_in, const int* in_sizes, int n_in,
                              void* d_out, int out_size)
{
    const float* x   = (const float*)d_in[0];
    const float* w_q = (const float*)d_in[1];
    const float* w_k = (const float*)d_in[2];
    const float* w_v = (const float*)d_in[3];
    const float* w_o = (const float*)d_in[4];
    const float* b_o = (const float*)d_in[5];
    float* out = (float*)d_out;

    float *q, *k, *v, *ao;
    cudaGetSymbolAddress((void**)&q,  g_q);
    cudaGetSymbolAddress((void**)&k,  g_k);
    cudaGetSymbolAddress((void**)&v,  g_v);
    cudaGetSymbolAddress((void**)&ao, g_ao);

    cudaFuncSetAttribute(gemm_mma, cudaFuncAttributeMaxDynamicSharedMemorySize, GSMEM);
    cudaFuncSetAttribute(attn_mma, cudaFuncAttributeMaxDynamicSharedMemorySize, ASMEM);

    dim3 ggrid(D_MODEL / 128, MROWS / 128);   // (8, 64)

    gemm_mma<<<ggrid, 256, GSMEM>>>(x, w_q, nullptr, q);
    gemm_mma<<<ggrid, 256, GSMEM>>>(x, w_k, nullptr, k);
    gemm_mma<<<ggrid, 256, GSMEM>>>(x, w_v, nullptr, v);

    dim3 agrid(SEQ / 128, BATCH * NHEADS);    // (16, 64)
    attn_mma<<<agrid, 256, ASMEM>>>(q, k, v, ao);

    gemm_mma<<<ggrid, 256, GSMEM>>>(ao, w_o, b_o, out);
}

// round 9
// speedup vs baseline: 3.5760x; 1.7739x over previous
#include <cuda_runtime.h>
#include <cuda_bf16.h>
#include <cstdint>

#define D_MODEL 1024
#define NHEADS  16
#define DK      64
#define BATCH   4
#define SEQ     2048
#define MROWS   (BATCH * SEQ)   // 8192

// -------- scratch (no allocations allowed; __device__ globals) --------
__device__ __nv_bfloat16 g_xh [MROWS * D_MODEL];
__device__ __nv_bfloat16 g_xl [MROWS * D_MODEL];
__device__ __nv_bfloat16 g_qh [MROWS * D_MODEL];
__device__ __nv_bfloat16 g_ql [MROWS * D_MODEL];
__device__ __nv_bfloat16 g_kh [MROWS * D_MODEL];
__device__ __nv_bfloat16 g_kl [MROWS * D_MODEL];
__device__ __nv_bfloat16 g_vh [MROWS * D_MODEL];
__device__ __nv_bfloat16 g_vl [MROWS * D_MODEL];
__device__ __nv_bfloat16 g_aoh[MROWS * D_MODEL];
__device__ __nv_bfloat16 g_aol[MROWS * D_MODEL];
__device__ __nv_bfloat16 g_wh [4][D_MODEL * D_MODEL];
__device__ __nv_bfloat16 g_wl [4][D_MODEL * D_MODEL];

// ======================================================================
// helpers
// ======================================================================
__device__ __forceinline__ uint32_t smem_u32(const void* p) {
    uint32_t a;
    asm("{ .reg .u64 t; cvta.to.shared.u64 t, %1; cvt.u32.u64 %0, t; }"
        : "=r"(a) : "l"(p));
    return a;
}

#define LDSM_X4(r0, r1, r2, r3, addr)                                         \
    asm volatile("ldmatrix.sync.aligned.m8n8.x4.shared.b16 {%0,%1,%2,%3}, [%4];" \
                 : "=r"(r0), "=r"(r1), "=r"(r2), "=r"(r3) : "r"(addr))

#define LDSM_X4_T(r0, r1, r2, r3, addr)                                       \
    asm volatile("ldmatrix.sync.aligned.m8n8.x4.trans.shared.b16 {%0,%1,%2,%3}, [%4];" \
                 : "=r"(r0), "=r"(r1), "=r"(r2), "=r"(r3) : "r"(addr))

#define MMA16816(d, a, b0v, b1v)                                              \
    asm volatile("mma.sync.aligned.m16n8k16.row.col.f32.bf16.bf16.f32 "       \
                 "{%0,%1,%2,%3}, {%4,%5,%6,%7}, {%8,%9}, {%0,%1,%2,%3};"      \
                 : "+f"((d)[0]), "+f"((d)[1]), "+f"((d)[2]), "+f"((d)[3])     \
                 : "r"((a)[0]), "r"((a)[1]), "r"((a)[2]), "r"((a)[3]),        \
                   "r"(b0v), "r"(b1v))

#define CP_ASYNC16(saddr, gptr)                                               \
    asm volatile("cp.async.cg.shared.global [%0], [%1], 16;"                  \
                 :: "r"(saddr), "l"(gptr))
#define CP_COMMIT() asm volatile("cp.async.commit_group;" ::: "memory")
#define CP_WAIT(n)  asm volatile("cp.async.wait_group %0;" :: "n"(n) : "memory")

// split one float pair into bf16 hi + bf16 lo packed u32s
__device__ __forceinline__ void split2(float x, float y, uint32_t& hi, uint32_t& lo) {
    __nv_bfloat162 h = __floats2bfloat162_rn(x, y);
    float2 f = __bfloat1622float2(h);
    __nv_bfloat162 l = __floats2bfloat162_rn(x - f.x, y - f.y);
    hi = *reinterpret_cast<uint32_t*>(&h);
    lo = *reinterpret_cast<uint32_t*>(&l);
}

// ======================================================================
// presplit: fp32 array -> bf16 hi/lo arrays. 4 elems per thread.
// ======================================================================
__global__ __launch_bounds__(256)
void presplit(const float* __restrict__ in,
              __nv_bfloat16* __restrict__ hi,
              __nv_bfloat16* __restrict__ lo)
{
    const int i = blockIdx.x * 256 + threadIdx.x;
    float4 v = *(const float4*)(in + (size_t)i * 4);
    uint2 h, l;
    split2(v.x, v.y, h.x, l.x);
    split2(v.z, v.w, h.y, l.y);
    *(uint2*)(hi + (size_t)i * 4) = h;
    *(uint2*)(lo + (size_t)i * 4) = l;
}

// ======================================================================
// HMMA GEMM on pre-split bf16: C = A @ B^T, bf16x3 split, cp.async staged.
// mode 0: fp32 out (+bias). mode 1: split bf16 out. mode 2: scale 1/8 + split.
// ======================================================================
#define GPITCH 80
#define GBK    32
#define GNIT   (D_MODEL / GBK)
#define MAT_B  (128 * GPITCH)          // 10240
#define BUF_B  (4 * MAT_B)             // 40960
#define GSMEM  (2 * BUF_B)             // 81920

__device__ __forceinline__ void gemm_stage(
    uint32_t sbase, uint32_t bufo, int tid, int koff,
    const __nv_bfloat16* Ah, const __nv_bfloat16* Al,
    const __nv_bfloat16* Bh, const __nv_bfloat16* Bl,
    int bm, int bn)
{
    #pragma unroll
    for (int i = 0; i < 2; i++) {
        const int id  = tid + 256 * i;      // 0..511
        const int row = id >> 2;
        const int c16 = id & 3;
        const uint32_t so = sbase + bufo + (uint32_t)(row * GPITCH + c16 * 16);
        const size_t ga = (size_t)(bm + row) * D_MODEL + koff + c16 * 8;
        const size_t gb = (size_t)(bn + row) * D_MODEL + koff + c16 * 8;
        CP_ASYNC16(so,             Ah + ga);
        CP_ASYNC16(so + MAT_B,     Al + ga);
        CP_ASYNC16(so + 2 * MAT_B, Bh + gb);
        CP_ASYNC16(so + 3 * MAT_B, Bl + gb);
    }
}

__global__ __launch_bounds__(256)
void gemm_mma(const __nv_bfloat16* __restrict__ Ah,
              const __nv_bfloat16* __restrict__ Al,
              const __nv_bfloat16* __restrict__ Bh,
              const __nv_bfloat16* __restrict__ Bl,
              const float* __restrict__ bias,
              float* __restrict__ C,
              __nv_bfloat16* __restrict__ Ch,
              __nv_bfloat16* __restrict__ Cl,
              int mode)
{
    extern __shared__ char sm[];
    const uint32_t sbase = smem_u32(sm);

    const int tid    = threadIdx.x;
    const int lane   = tid & 31;
    const int wid    = tid >> 5;
    const int warp_m = wid & 3;
    const int warp_n = wid >> 2;
    const int bm     = blockIdx.y * 128;
    const int bn     = blockIdx.x * 128;

    float acc[2][8][4];
    #pragma unroll
    for (int i = 0; i < 2; i++)
        #pragma unroll
        for (int j = 0; j < 8; j++)
            #pragma unroll
            for (int r = 0; r < 4; r++) acc[i][j][r] = 0.f;

    const uint32_t a_l = sbase + (uint32_t)((warp_m * 32 + (lane & 15)) * GPITCH
                                            + (lane >> 4) * 16);
    const int bnl = warp_n * 64 + (lane & 7) + ((lane >> 4) << 3);
    const uint32_t b_l = sbase + 2 * MAT_B + (uint32_t)(bnl * GPITCH
                                            + ((lane >> 3) & 1) * 16);

    gemm_stage(sbase, 0, tid, 0, Ah, Al, Bh, Bl, bm, bn);
    CP_COMMIT();

    #pragma unroll 1
    for (int it = 0; it < GNIT; it++) {
        const uint32_t bufo = (uint32_t)(it & 1) * BUF_B;
        if (it + 1 < GNIT) {
            gemm_stage(sbase, (uint32_t)((it + 1) & 1) * BUF_B, tid,
                       (it + 1) * GBK, Ah, Al, Bh, Bl, bm, bn);
            CP_COMMIT();
            CP_WAIT(1);
        } else {
            CP_WAIT(0);
        }
        __syncthreads();

        #pragma unroll
        for (int ks = 0; ks < 2; ks++) {
            const uint32_t ko = (uint32_t)(ks * 32);
            uint32_t ah[2][4], al[2][4];
            #pragma unroll
            for (int im = 0; im < 2; im++) {
                uint32_t aa = a_l + bufo + ko + (uint32_t)(im * 16 * GPITCH);
                LDSM_X4(ah[im][0], ah[im][1], ah[im][2], ah[im][3], aa);
                LDSM_X4(al[im][0], al[im][1], al[im][2], al[im][3], aa + MAT_B);
            }
            uint32_t bh[16], bl[16];
            #pragma unroll
            for (int pn = 0; pn < 4; pn++) {
                uint32_t ba = b_l + bufo + ko + (uint32_t)(pn * 16 * GPITCH);
                LDSM_X4(bh[4 * pn + 0], bh[4 * pn + 1], bh[4 * pn + 2], bh[4 * pn + 3], ba);
                LDSM_X4(bl[4 * pn + 0], bl[4 * pn + 1], bl[4 * pn + 2], bl[4 * pn + 3], ba + MAT_B);
            }
            #pragma unroll
            for (int im = 0; im < 2; im++)
                #pragma unroll
                for (int in = 0; in < 8; in++) {
                    MMA16816(acc[im][in], ah[im], bh[2 * in], bh[2 * in + 1]);
                    MMA16816(acc[im][in], ah[im], bl[2 * in], bl[2 * in + 1]);
                    MMA16816(acc[im][in], al[im], bh[2 * in], bh[2 * in + 1]);
                }
        }
        __syncthreads();
    }

    const int g  = lane >> 2;
    const int q4 = (lane & 3) * 2;
    if (mode == 0) {
        #pragma unroll
        for (int im = 0; im < 2; im++) {
            const int r0 = bm + warp_m * 32 + im * 16 + g;
            #pragma unroll
            for (int in = 0; in < 8; in++) {
                const int c = bn + warp_n * 64 + in * 8 + q4;
                const float b0 = bias[c], b1 = bias[c + 1];
                *(float2*)(C + (size_t)r0 * D_MODEL + c) =
                    make_float2(acc[im][in][0] + b0, acc[im][in][1] + b1);
                *(float2*)(C + (size_t)(r0 + 8) * D_MODEL + c) =
                    make_float2(acc[im][in][2] + b0, acc[im][in][3] + b1);
            }
        }
    } else {
        const float s = (mode == 2) ? 0.125f : 1.f;
        #pragma unroll
        for (int im = 0; im < 2; im++) {
            const int r0 = bm + warp_m * 32 + im * 16 + g;
            #pragma unroll
            for (int in = 0; in < 8; in++) {
                const int c = bn + warp_n * 64 + in * 8 + q4;
                uint32_t h, l;
                split2(acc[im][in][0] * s, acc[im][in][1] * s, h, l);
                *(uint32_t*)(Ch + (size_t)r0 * D_MODEL + c) = h;
                *(uint32_t*)(Cl + (size_t)r0 * D_MODEL + c) = l;
                split2(acc[im][in][2] * s, acc[im][in][3] * s, h, l);
                *(uint32_t*)(Ch + (size_t)(r0 + 8) * D_MODEL + c) = h;
                *(uint32_t*)(Cl + (size_t)(r0 + 8) * D_MODEL + c) = l;
            }
        }
    }
}

// ======================================================================
// Tensor-core causal flash attention on pre-split bf16 inputs.
// Q staged once; K/V double-buffered via cp.async. Writes split ao.
// ======================================================================
#define APITCH 144
#define SQH   0
#define SQL   (128 * APITCH)            // 18432
#define KV0   (2 * 128 * APITCH)        // 36864
#define KVMAT (64 * APITCH)             // 9216 per matrix
#define KVBUF (4 * KVMAT)               // 36864 (KH, KL, VH, VL)
#define ASMEM (KV0 + 2 * KVBUF)         // 110592

__device__ __forceinline__ void attn_stage_kv(
    uint32_t dst, int tid, const __nv_bfloat16* Kh, const __nv_bfloat16* Kl,
    const __nv_bfloat16* Vh, const __nv_bfloat16* Vl,
    size_t gbase, int k0)
{
    #pragma unroll
    for (int i = 0; i < 2; i++) {
        const int id  = tid + 256 * i;        // 0..511
        const int row = id >> 3;              // 0..63
        const int c16 = id & 7;
        const uint32_t so = dst + (uint32_t)(row * APITCH + c16 * 16);
        const size_t gk = gbase + (size_t)(k0 + row) * D_MODEL + c16 * 8;
        CP_ASYNC16(so,             Kh + gk);
        CP_ASYNC16(so + KVMAT,     Kl + gk);
        CP_ASYNC16(so + 2 * KVMAT, Vh + gk);
        CP_ASYNC16(so + 3 * KVMAT, Vl + gk);
    }
}

__global__ __launch_bounds__(256)
void attn_mma(const __nv_bfloat16* __restrict__ Qh,
              const __nv_bfloat16* __restrict__ Ql,
              const __nv_bfloat16* __restrict__ Kh,
              const __nv_bfloat16* __restrict__ Kl,
              const __nv_bfloat16* __restrict__ Vh,
              const __nv_bfloat16* __restrict__ Vl,
              __nv_bfloat16* __restrict__ Oh,
              __nv_bfloat16* __restrict__ Ol)
{
    extern __shared__ char sm[];
    const uint32_t sbase = smem_u32(sm);

    const int tid  = threadIdx.x;
    const int lane = tid & 31;
    const int wid  = tid >> 5;
    const int g    = lane >> 2;
    const int tg   = lane & 3;
    const int qb   = blockIdx.x;
    const int bh   = blockIdx.y;
    const size_t base = (size_t)(bh >> 4) * SEQ * D_MODEL + (size_t)(bh & 15) * DK;

    const int qbase = qb * 128 + wid * 16;

    // ---- stage Q (cp.async, once) ----
    #pragma unroll
    for (int i = 0; i < 4; i++) {
        const int id  = tid + 256 * i;        // 0..1023
        const int row = id >> 3;              // 0..127
        const int c16 = id & 7;
        const uint32_t so = sbase + (uint32_t)(row * APITCH + c16 * 16);
        const size_t gq = base + (size_t)(qb * 128 + row) * D_MODEL + c16 * 8;
        CP_ASYNC16(so,       Qh + gq);
        CP_ASYNC16(so + SQL, Ql + gq);
    }
    attn_stage_kv(sbase + KV0, tid, Kh, Kl, Vh, Vl, base, 0);
    CP_COMMIT();

    float oacc[8][4];
    #pragma unroll
    for (int i = 0; i < 8; i++)
        #pragma unroll
        for (int r = 0; r < 4; r++) oacc[i][r] = 0.f;
    float m0 = -1e30f, m1 = -1e30f, l0 = 0.f, l1 = 0.f;

    const uint32_t qa = sbase + (uint32_t)((wid * 16 + (lane & 15)) * APITCH
                                           + (lane >> 4) * 16);
    const uint32_t ka_l = (uint32_t)(((lane & 7) + ((lane >> 4) << 3)) * APITCH
                                           + ((lane >> 3) & 1) * 16);
    const uint32_t va_l = (uint32_t)((lane & 15) * APITCH + (lane >> 4) * 16);

    const int ntiles = 2 * qb + 2;

    #pragma unroll 1
    for (int t = 0; t < ntiles; t++) {
        const int k0 = t * 64;
        const uint32_t kvb = sbase + KV0 + (uint32_t)(t & 1) * KVBUF;

        if (t + 1 < ntiles) {
            attn_stage_kv(sbase + KV0 + (uint32_t)((t + 1) & 1) * KVBUF,
                          tid, Kh, Kl, Vh, Vl, base, (t + 1) * 64);
            CP_COMMIT();
            CP_WAIT(1);
        } else {
            CP_WAIT(0);
        }
        __syncthreads();

        const bool active = (k0 <= qbase + 15);
        if (active) {
            // ---- S = Q @ K^T (3-term split) ----
            float sacc[8][4];
            #pragma unroll
            for (int i = 0; i < 8; i++)
                #pragma unroll
                for (int r = 0; r < 4; r++) sacc[i][r] = 0.f;

            const uint32_t ka = kvb + ka_l;
            #pragma unroll
            for (int kk = 0; kk < 4; kk++) {
                const uint32_t ko = (uint32_t)(kk * 32);
                uint32_t ah[4], al[4];
                LDSM_X4(ah[0], ah[1], ah[2], ah[3], qa + ko);
                LDSM_X4(al[0], al[1], al[2], al[3], qa + ko + SQL);
                #pragma unroll
                for (int nt = 0; nt < 4; nt++) {
                    uint32_t ba = ka + ko + (uint32_t)(nt * 16 * APITCH);
                    uint32_t kh[4], kl[4];
                    LDSM_X4(kh[0], kh[1], kh[2], kh[3], ba);
                    LDSM_X4(kl[0], kl[1], kl[2], kl[3], ba + KVMAT);
                    MMA16816(sacc[2*nt],   ah, kh[0], kh[1]);
                    MMA16816(sacc[2*nt],   ah, kl[0], kl[1]);
                    MMA16816(sacc[2*nt],   al, kh[0], kh[1]);
                    MMA16816(sacc[2*nt+1], ah, kh[2], kh[3]);
                    MMA16816(sacc[2*nt+1], ah, kl[2], kl[3]);
                    MMA16816(sacc[2*nt+1], al, kh[2], kh[3]);
                }
            }

            // ---- causal mask ----
            if (t + 2 >= ntiles) {
                const int qi0 = qbase + g;
                const int qi1 = qbase + g + 8;
                #pragma unroll
                for (int dn = 0; dn < 8; dn++) {
                    const int kc = k0 + dn * 8 + tg * 2;
                    if (kc     > qi0) sacc[dn][0] = -1e30f;
                    if (kc + 1 > qi0) sacc[dn][1] = -1e30f;
                    if (kc     > qi1) sacc[dn][2] = -1e30f;
                    if (kc + 1 > qi1) sacc[dn][3] = -1e30f;
                }
            }

            // ---- online softmax ----
            float r0 = -1e30f, r1 = -1e30f;
            #pragma unroll
            for (int dn = 0; dn < 8; dn++) {
                r0 = fmaxf(r0, fmaxf(sacc[dn][0], sacc[dn][1]));
                r1 = fmaxf(r1, fmaxf(sacc[dn][2], sacc[dn][3]));
            }
            r0 = fmaxf(r0, __shfl_xor_sync(0xFFFFFFFFu, r0, 1));
            r0 = fmaxf(r0, __shfl_xor_sync(0xFFFFFFFFu, r0, 2));
            r1 = fmaxf(r1, __shfl_xor_sync(0xFFFFFFFFu, r1, 1));
            r1 = fmaxf(r1, __shfl_xor_sync(0xFFFFFFFFu, r1, 2));
            const float nm0 = fmaxf(m0, r0), nm1 = fmaxf(m1, r1);
            const float c0 = __expf(m0 - nm0), c1 = __expf(m1 - nm1);
            m0 = nm0; m1 = nm1;
            l0 *= c0;  l1 *= c1;
            #pragma unroll
            for (int dn = 0; dn < 8; dn++) {
                oacc[dn][0] *= c0; oacc[dn][1] *= c0;
                oacc[dn][2] *= c1; oacc[dn][3] *= c1;
            }
            #pragma unroll
            for (int dn = 0; dn < 8; dn++) {
                float p0 = __expf(sacc[dn][0] - m0);
                float p1 = __expf(sacc[dn][1] - m0);
                float p2 = __expf(sacc[dn][2] - m1);
                float p3 = __expf(sacc[dn][3] - m1);
                sacc[dn][0] = p0; sacc[dn][1] = p1;
                sacc[dn][2] = p2; sacc[dn][3] = p3;
                l0 += p0 + p1; l1 += p2 + p3;
            }

            // ---- O += P @ V (3-term split) ----
            const uint32_t va = kvb + 2 * KVMAT + va_l;
            #pragma unroll
            for (int kk = 0; kk < 4; kk++) {
                uint32_t ph[4], pl[4];
                split2(sacc[2*kk][0],   sacc[2*kk][1],   ph[0], pl[0]);
                split2(sacc[2*kk][2],   sacc[2*kk][3],   ph[1], pl[1]);
                split2(sacc[2*kk+1][0], sacc[2*kk+1][1], ph[2], pl[2]);
                split2(sacc[2*kk+1][2], sacc[2*kk+1][3], ph[3], pl[3]);
                #pragma unroll
                for (int dn = 0; dn < 4; dn++) {
                    uint32_t a = va + (uint32_t)(kk * 16 * APITCH + dn * 32);
                    uint32_t vh[4], vl[4];
                    LDSM_X4_T(vh[0], vh[1], vh[2], vh[3], a);
                    LDSM_X4_T(vl[0], vl[1], vl[2], vl[3], a + KVMAT);
                    MMA16816(oacc[2*dn],   ph, vh[0], vh[1]);
                    MMA16816(oacc[2*dn],   ph, vl[0], vl[1]);
                    MMA16816(oacc[2*dn],   pl, vh[0], vh[1]);
                    MMA16816(oacc[2*dn+1], ph, vh[2], vh[3]);
                    MMA16816(oacc[2*dn+1], ph, vl[2], vl[3]);
                    MMA16816(oacc[2*dn+1], pl, vh[2], vh[3]);
                }
            }
        }
        __syncthreads();
    }

    // ---- epilogue: normalize, split, store ----
    l0 += __shfl_xor_sync(0xFFFFFFFFu, l0, 1);
    l0 += __shfl_xor_sync(0xFFFFFFFFu, l0, 2);
    l1 += __shfl_xor_sync(0xFFFFFFFFu, l1, 1);
    l1 += __shfl_xor_sync(0xFFFFFFFFu, l1, 2);
    const float inv0 = 1.f / l0, inv1 = 1.f / l1;

    const size_t o0 = base + (size_t)(qbase + g) * D_MODEL + tg * 2;
    const size_t o1 = o0 + 8 * D_MODEL;
    #pragma unroll
    for (int dn = 0; dn < 8; dn++) {
        uint32_t h, l;
        split2(oacc[dn][0] * inv0, oacc[dn][1] * inv0, h, l);
        *(uint32_t*)(Oh + o0 + dn * 8) = h;
        *(uint32_t*)(Ol + o0 + dn * 8) = l;
        split2(oacc[dn][2] * inv1, oacc[dn][3] * inv1, h, l);
        *(uint32_t*)(Oh + o1 + dn * 8) = h;
        *(uint32_t*)(Ol + o1 + dn * 8) = l;
    }
}

// ======================================================================
extern "C" void kernel_launch(void* const* d_in, const int* in_sizes, int n_in,
                              void* d_out, int out_size)
{
    const float* x   = (const float*)d_in[0];
    const float* w_q = (const float*)d_in[1];
    const float* w_k = (const float*)d_in[2];
    const float* w_v = (const float*)d_in[3];
    const float* w_o = (const float*)d_in[4];
    const float* b_o = (const float*)d_in[5];
    float* out = (float*)d_out;

    __nv_bfloat16 *xh, *xl, *qh, *ql, *kh, *kl, *vh, *vl, *aoh, *aol, *wh, *wl;
    cudaGetSymbolAddress((void**)&xh,  g_xh);
    cudaGetSymbolAddress((void**)&xl,  g_xl);
    cudaGetSymbolAddress((void**)&qh,  g_qh);
    cudaGetSymbolAddress((void**)&ql,  g_ql);
    cudaGetSymbolAddress((void**)&kh,  g_kh);
    cudaGetSymbolAddress((void**)&kl,  g_kl);
    cudaGetSymbolAddress((void**)&vh,  g_vh);
    cudaGetSymbolAddress((void**)&vl,  g_vl);
    cudaGetSymbolAddress((void**)&aoh, g_aoh);
    cudaGetSymbolAddress((void**)&aol, g_aol);
    cudaGetSymbolAddress((void**)&wh,  g_wh);
    cudaGetSymbolAddress((void**)&wl,  g_wl);

    cudaFuncSetAttribute(gemm_mma, cudaFuncAttributeMaxDynamicSharedMemorySize, GSMEM);
    cudaFuncSetAttribute(attn_mma, cudaFuncAttributeMaxDynamicSharedMemorySize, ASMEM);

    const int WN = D_MODEL * D_MODEL;

    presplit<<<MROWS * D_MODEL / 1024, 256>>>(x, xh, xl);
    presplit<<<WN / 1024, 256>>>(w_q, wh + 0 * (size_t)WN, wl + 0 * (size_t)WN);
    presplit<<<WN / 1024, 256>>>(w_k, wh + 1 * (size_t)WN, wl + 1 * (size_t)WN);
    presplit<<<WN / 1024, 256>>>(w_v, wh + 2 * (size_t)WN, wl + 2 * (size_t)WN);
    presplit<<<WN / 1024, 256>>>(w_o, wh + 3 * (size_t)WN, wl + 3 * (size_t)WN);

    dim3 ggrid(D_MODEL / 128, MROWS / 128);   // (8, 64)

    gemm_mma<<<ggrid, 256, GSMEM>>>(xh, xl, wh + 0 * (size_t)WN, wl + 0 * (size_t)WN,
                                    nullptr, nullptr, qh, ql, 2);
    gemm_mma<<<ggrid, 256, GSMEM>>>(xh, xl, wh + 1 * (size_t)WN, wl + 1 * (size_t)WN,
                                    nullptr, nullptr, kh, kl, 1);
    gemm_mma<<<ggrid, 256, GSMEM>>>(xh, xl, wh + 2 * (size_t)WN, wl + 2 * (size_t)WN,
                                    nullptr, nullptr, vh, vl, 1);

    dim3 agrid(SEQ / 128, BATCH * NHEADS);    // (16, 64)
    attn_mma<<<agrid, 256, ASMEM>>>(qh, ql, kh, kl, vh, vl, aoh, aol);

    gemm_mma<<<ggrid, 256, GSMEM>>>(aoh, aol, wh + 3 * (size_t)WN, wl + 3 * (size_t)WN,
                                    b_o, out, nullptr, nullptr, 0);
}